// round 1
// baseline (speedup 1.0000x reference)
#include <cuda_runtime.h>
#include <math.h>

#define HEADS   8
#define DK      64
#define DV      64
#define NSEQ    49
#define GRID7   7
#define DMODEL  512
#define BATCH   2048
#define MROWS   (BATCH * NSEQ)   // 100352

// ---------------- scratch (no allocations allowed) ----------------
__device__ float g_q[(size_t)MROWS * DMODEL];
__device__ float g_k[(size_t)MROWS * DMODEL];
__device__ float g_v[(size_t)MROWS * DMODEL];
__device__ float g_att[(size_t)MROWS * DMODEL];

// ---------------- classic tiled SGEMM: C[m][n] = sum_k A[m][k]*W[n][k] + bias[n] ----------------
// A: [M,K] row-major, W: [N,K] row-major (i.e. we compute A @ W^T), C: [M,N].
// Requires M % BM == 0, N % BN == 0, K % BK == 0 (true for all our shapes).
template <int BM, int BN, int BK, int TM, int TN>
__global__ __launch_bounds__((BM / TM) * (BN / TN))
void sgemm_bias_kernel(const float* __restrict__ A,
                       const float* __restrict__ W,
                       const float* __restrict__ bias,
                       float* __restrict__ C,
                       int M, int N, int K)
{
    constexpr int NTHREADS = (BM / TM) * (BN / TN);
    __shared__ float As[BK][BM];   // transposed A tile
    __shared__ float Bs[BK][BN];   // transposed W tile

    const int tid = threadIdx.x;
    const int tx  = tid % (BN / TN);
    const int ty  = tid / (BN / TN);
    const int m0  = blockIdx.y * BM;
    const int n0  = blockIdx.x * BN;

    float acc[TM][TN];
#pragma unroll
    for (int i = 0; i < TM; i++)
#pragma unroll
        for (int j = 0; j < TN; j++) acc[i][j] = 0.0f;

    for (int k0 = 0; k0 < K; k0 += BK) {
        // Load A tile: BM x BK, one float4 per thread slot, store transposed.
#pragma unroll
        for (int idx = tid * 4; idx < BM * BK; idx += NTHREADS * 4) {
            int row = idx / BK;
            int col = idx % BK;
            float4 t = *reinterpret_cast<const float4*>(
                &A[(size_t)(m0 + row) * K + k0 + col]);
            As[col + 0][row] = t.x;
            As[col + 1][row] = t.y;
            As[col + 2][row] = t.z;
            As[col + 3][row] = t.w;
        }
        // Load W tile: BN x BK (K contiguous), store transposed.
#pragma unroll
        for (int idx = tid * 4; idx < BN * BK; idx += NTHREADS * 4) {
            int row = idx / BK;
            int col = idx % BK;
            float4 t = *reinterpret_cast<const float4*>(
                &W[(size_t)(n0 + row) * K + k0 + col]);
            Bs[col + 0][row] = t.x;
            Bs[col + 1][row] = t.y;
            Bs[col + 2][row] = t.z;
            Bs[col + 3][row] = t.w;
        }
        __syncthreads();

#pragma unroll
        for (int k = 0; k < BK; k++) {
            float a_frag[TM], b_frag[TN];
            // vectorized smem fragment reads (LDS.128) -> conflict-free
#pragma unroll
            for (int i = 0; i < TM; i += 4) {
                float4 t = *reinterpret_cast<const float4*>(&As[k][ty * TM + i]);
                a_frag[i + 0] = t.x; a_frag[i + 1] = t.y;
                a_frag[i + 2] = t.z; a_frag[i + 3] = t.w;
            }
#pragma unroll
            for (int j = 0; j < TN; j += 4) {
                float4 t = *reinterpret_cast<const float4*>(&Bs[k][tx * TN + j]);
                b_frag[j + 0] = t.x; b_frag[j + 1] = t.y;
                b_frag[j + 2] = t.z; b_frag[j + 3] = t.w;
            }
#pragma unroll
            for (int i = 0; i < TM; i++)
#pragma unroll
                for (int j = 0; j < TN; j++)
                    acc[i][j] += a_frag[i] * b_frag[j];
        }
        __syncthreads();
    }

    // Epilogue: bias + vectorized store.
#pragma unroll
    for (int i = 0; i < TM; i++) {
        int m = m0 + ty * TM + i;
#pragma unroll
        for (int j = 0; j < TN; j += 4) {
            int n = n0 + tx * TN + j;
            float4 t;
            t.x = acc[i][j + 0] + bias[n + 0];
            t.y = acc[i][j + 1] + bias[n + 1];
            t.z = acc[i][j + 2] + bias[n + 2];
            t.w = acc[i][j + 3] + bias[n + 3];
            *reinterpret_cast<float4*>(&C[(size_t)m * N + n]) = t;
        }
    }
}

// ---------------- per-(b,h) dilated attention ----------------
// mask[i][j] for p=1 reduces to: Chebyshev distance on 7x7 grid == 1
// (the Manhattan condition is implied). Mask is MULTIPLICATIVE on logits
// (masked logits = 0, still fed through softmax as exp(0)).
__global__ __launch_bounds__(256)
void dilate_attention_kernel(float* __restrict__ out)
{
    __shared__ float qs[NSEQ * DK];
    __shared__ float ks[NSEQ * (DK + 1)];  // +1 pad: kills 32-way conflicts in QK^T
    __shared__ float vs[NSEQ * DV];
    __shared__ float S[NSEQ][NSEQ + 1];

    const int h   = blockIdx.x;
    const int b   = blockIdx.y;
    const int tid = threadIdx.x;
    const size_t base = (size_t)b * NSEQ * DMODEL + (size_t)h * DK;

    // load q,k,v tiles (coalesced: 64 consecutive floats per row)
    for (int e = tid; e < NSEQ * DK; e += 256) {
        int n = e / DK, d = e % DK;
        size_t g = base + (size_t)n * DMODEL + d;
        qs[e]                 = g_q[g];
        ks[n * (DK + 1) + d]  = g_k[g];
        vs[e]                 = g_v[g];
    }
    __syncthreads();

    // S = (q @ k^T) * mask / sqrt(64)
    for (int e = tid; e < NSEQ * NSEQ; e += 256) {
        int i = e / NSEQ, j = e % NSEQ;
        int dr = abs(i / GRID7 - j / GRID7);
        int dc = abs(i % GRID7 - j % GRID7);
        bool m = (max(dr, dc) == 1);
        float dot = 0.0f;
#pragma unroll
        for (int d = 0; d < DK; d++)
            dot += qs[i * DK + d] * ks[j * (DK + 1) + d];
        S[i][j] = m ? dot * 0.125f : 0.0f;
    }
    __syncthreads();

    // row softmax (49 rows, one thread each)
    if (tid < NSEQ) {
        float mx = -1e30f;
#pragma unroll
        for (int j = 0; j < NSEQ; j++) mx = fmaxf(mx, S[tid][j]);
        float sum = 0.0f;
#pragma unroll
        for (int j = 0; j < NSEQ; j++) {
            float ev = __expf(S[tid][j] - mx);
            S[tid][j] = ev;
            sum += ev;
        }
        float inv = 1.0f / sum;
#pragma unroll
        for (int j = 0; j < NSEQ; j++) S[tid][j] *= inv;
    }
    __syncthreads();

    // O = att @ v, written in (b, n, h*DV + d) layout for the output GEMM
    for (int e = tid; e < NSEQ * DV; e += 256) {
        int i = e / DV, d = e % DV;
        float acc = 0.0f;
#pragma unroll
        for (int j = 0; j < NSEQ; j++)
            acc += S[i][j] * vs[j * DV + d];
        out[base + (size_t)i * DMODEL + d] = acc;
    }
}

// ---------------- launch ----------------
extern "C" void kernel_launch(void* const* d_in, const int* in_sizes, int n_in,
                              void* d_out, int out_size)
{
    const float* queries = (const float*)d_in[0];
    const float* keys    = (const float*)d_in[1];
    const float* values  = (const float*)d_in[2];
    const float* Wq      = (const float*)d_in[3];
    const float* bq      = (const float*)d_in[4];
    const float* Wk      = (const float*)d_in[5];
    const float* bk      = (const float*)d_in[6];
    const float* Wv      = (const float*)d_in[7];
    const float* bv      = (const float*)d_in[8];
    const float* Wo      = (const float*)d_in[9];
    const float* bo      = (const float*)d_in[10];

    float *q, *k, *v, *att;
    cudaGetSymbolAddress((void**)&q,   g_q);
    cudaGetSymbolAddress((void**)&k,   g_k);
    cudaGetSymbolAddress((void**)&v,   g_v);
    cudaGetSymbolAddress((void**)&att, g_att);

    // QKV projections: M=100352, N=512, K=512
    dim3 gridQKV(DMODEL / 128, MROWS / 128);
    sgemm_bias_kernel<128, 128, 8, 8, 8><<<gridQKV, 256>>>(
        queries, Wq, bq, q, MROWS, DMODEL, DMODEL);
    sgemm_bias_kernel<128, 128, 8, 8, 8><<<gridQKV, 256>>>(
        keys, Wk, bk, k, MROWS, DMODEL, DMODEL);
    sgemm_bias_kernel<128, 128, 8, 8, 8><<<gridQKV, 256>>>(
        values, Wv, bv, v, MROWS, DMODEL, DMODEL);

    // attention: one block per (b, h)
    dilate_attention_kernel<<<dim3(HEADS, BATCH), 256>>>(att);

    // output projection: M=100352, N=64, K=512
    dim3 gridO(64 / 64, MROWS / 128);
    sgemm_bias_kernel<128, 64, 8, 8, 4><<<gridO, 256>>>(
        att, Wo, bo, (float*)d_out, MROWS, 64, DMODEL);
}

// round 2
// speedup vs baseline: 1.3180x; 1.3180x over previous
#include <cuda_runtime.h>
#include <mma.h>
#include <math.h>

using namespace nvcuda;

#define HEADS   8
#define DK      64
#define DV      64
#define NSEQ    49
#define GRID7   7
#define DMODEL  512
#define BATCH   2048
#define MROWS   (BATCH * NSEQ)   // 100352

// ---------------- scratch (no allocations allowed) ----------------
__device__ float g_q[(size_t)MROWS * DMODEL];
__device__ float g_k[(size_t)MROWS * DMODEL];
__device__ float g_v[(size_t)MROWS * DMODEL];
__device__ float g_att[(size_t)MROWS * DMODEL];

// =====================================================================
// tf32 WMMA GEMM:  C[M,N] = A[M,K] @ W[N,K]^T + bias
// A row-major, W row-major [N,K] (so B = W^T is col-major with ld=K).
// BM x BN block tile, BK k-chunk, 8 warps (256 threads), warp grid 4x2.
// =====================================================================
template <int BM, int BN, int BK>
__global__ __launch_bounds__(256)
void wmma_tf32_gemm(const float* __restrict__ A,
                    const float* __restrict__ W,
                    const float* __restrict__ bias,
                    float* __restrict__ C,
                    int M, int N, int K)
{
    constexpr int BKP     = BK + 4;          // padded smem stride (mult of 4)
    constexpr int WARPS_M = 4;
    constexpr int WARPS_N = 2;
    constexpr int WM      = BM / WARPS_M;    // 32
    constexpr int WN      = BN / WARPS_N;    // 64 (BN=128) or 32 (BN=64)
    constexpr int MF      = WM / 16;         // 2
    constexpr int NF      = WN / 16;         // 4 or 2

    __shared__ float As[BM][BKP];
    __shared__ float Ws[BN][BKP];
    __shared__ float stage[8][16][20];       // per-warp epilogue staging

    const int tid  = threadIdx.x;
    const int warp = tid >> 5;
    const int lane = tid & 31;
    const int wm   = warp / WARPS_N;
    const int wn   = warp % WARPS_N;

    const int m0 = blockIdx.y * BM;
    const int n0 = blockIdx.x * BN;

    wmma::fragment<wmma::accumulator, 16, 16, 8, float> acc[MF][NF];
#pragma unroll
    for (int mf = 0; mf < MF; mf++)
#pragma unroll
        for (int nf = 0; nf < NF; nf++)
            wmma::fill_fragment(acc[mf][nf], 0.0f);

    for (int k0 = 0; k0 < K; k0 += BK) {
        // ---- load A tile (BM x BK) as float4 ----
#pragma unroll
        for (int idx = tid; idx < BM * BK / 4; idx += 256) {
            int row = idx / (BK / 4);
            int col = (idx % (BK / 4)) * 4;
            float4 t = *reinterpret_cast<const float4*>(
                &A[(size_t)(m0 + row) * K + k0 + col]);
            *reinterpret_cast<float4*>(&As[row][col]) = t;
        }
        // ---- load W tile (BN x BK) as float4 ----
#pragma unroll
        for (int idx = tid; idx < BN * BK / 4; idx += 256) {
            int row = idx / (BK / 4);
            int col = (idx % (BK / 4)) * 4;
            float4 t = *reinterpret_cast<const float4*>(
                &W[(size_t)(n0 + row) * K + k0 + col]);
            *reinterpret_cast<float4*>(&Ws[row][col]) = t;
        }
        __syncthreads();

#pragma unroll
        for (int ks = 0; ks < BK; ks += 8) {
            wmma::fragment<wmma::matrix_a, 16, 16, 8,
                           wmma::precision::tf32, wmma::row_major> af[MF];
            wmma::fragment<wmma::matrix_b, 16, 16, 8,
                           wmma::precision::tf32, wmma::col_major> bf[NF];
#pragma unroll
            for (int mf = 0; mf < MF; mf++) {
                wmma::load_matrix_sync(af[mf], &As[wm * WM + mf * 16][ks], BKP);
#pragma unroll
                for (int e = 0; e < af[mf].num_elements; e++)
                    af[mf].x[e] = wmma::__float_to_tf32(af[mf].x[e]);
            }
#pragma unroll
            for (int nf = 0; nf < NF; nf++) {
                wmma::load_matrix_sync(bf[nf], &Ws[wn * WN + nf * 16][ks], BKP);
#pragma unroll
                for (int e = 0; e < bf[nf].num_elements; e++)
                    bf[nf].x[e] = wmma::__float_to_tf32(bf[nf].x[e]);
            }
#pragma unroll
            for (int mf = 0; mf < MF; mf++)
#pragma unroll
                for (int nf = 0; nf < NF; nf++)
                    wmma::mma_sync(acc[mf][nf], af[mf], bf[nf], acc[mf][nf]);
        }
        __syncthreads();
    }

    // ---- epilogue: stage each 16x16 fragment, add bias, vector store ----
#pragma unroll
    for (int mf = 0; mf < MF; mf++)
#pragma unroll
        for (int nf = 0; nf < NF; nf++) {
            wmma::store_matrix_sync(&stage[warp][0][0], acc[mf][nf], 20,
                                    wmma::mem_row_major);
            __syncwarp();
            int r  = lane >> 1;
            int c  = (lane & 1) * 8;
            int gm = m0 + wm * WM + mf * 16 + r;
            int gn = n0 + wn * WN + nf * 16 + c;
            float4 v0 = *reinterpret_cast<float4*>(&stage[warp][r][c]);
            float4 v1 = *reinterpret_cast<float4*>(&stage[warp][r][c + 4]);
            float4 b0 = *reinterpret_cast<const float4*>(&bias[gn]);
            float4 b1 = *reinterpret_cast<const float4*>(&bias[gn + 4]);
            v0.x += b0.x; v0.y += b0.y; v0.z += b0.z; v0.w += b0.w;
            v1.x += b1.x; v1.y += b1.y; v1.z += b1.z; v1.w += b1.w;
            *reinterpret_cast<float4*>(&C[(size_t)gm * N + gn])     = v0;
            *reinterpret_cast<float4*>(&C[(size_t)gm * N + gn + 4]) = v1;
            __syncwarp();
        }
}

// =====================================================================
// Sparse dilated attention.
// Multiplicative mask => masked logits are 0, exp(0)=1. So:
//   w_ij = exp(s_ij) - 1   for the <=8 Chebyshev-1 neighbors,
//   O_i  = (Vsum + sum_j w_ij v_j) / (49 + sum_j w_ij)
// Only 49x8 dot products needed instead of 49x49.
// =====================================================================
__global__ __launch_bounds__(256)
void dilate_attention_sparse(const float* __restrict__ q,
                             const float* __restrict__ k,
                             const float* __restrict__ v,
                             float* __restrict__ out)
{
    __shared__ float qs[NSEQ * DK];
    __shared__ float ks[NSEQ * (DK + 1)];   // pad kills QK bank conflicts
    __shared__ float vs[NSEQ * DV];
    __shared__ float wgt[NSEQ][8];          // exp(s)-1 (0 for empty slots)
    __shared__ float zinv[NSEQ];
    __shared__ float vsum[DV];
    __shared__ int   nbr[NSEQ][8];
    __shared__ int   cnt[NSEQ];

    const int h   = blockIdx.x;
    const int b   = blockIdx.y;
    const int tid = threadIdx.x;
    const size_t base = (size_t)b * NSEQ * DMODEL + (size_t)h * DK;

    // ---- load q,k,v tiles (coalesced 64-float rows) ----
    for (int e = tid; e < NSEQ * DK; e += 256) {
        int n = e >> 6, d = e & 63;
        size_t g = base + (size_t)n * DMODEL + d;
        qs[e]                = q[g];
        ks[n * (DK + 1) + d] = k[g];
        vs[e]                = v[g];
    }
    // ---- neighbor lists (threads 0..48) ----
    if (tid < NSEQ) {
        int r = tid / GRID7, c = tid % GRID7;
        int n = 0;
#pragma unroll
        for (int dr = -1; dr <= 1; dr++)
#pragma unroll
            for (int dc = -1; dc <= 1; dc++) {
                if (dr == 0 && dc == 0) continue;
                int rr = r + dr, cc = c + dc;
                if (rr >= 0 && rr < GRID7 && cc >= 0 && cc < GRID7)
                    nbr[tid][n++] = rr * GRID7 + cc;
            }
        cnt[tid] = n;
        for (int l = n; l < 8; l++) nbr[tid][l] = 0;   // dummy (weight=0)
    }
    __syncthreads();

    // ---- Vsum (threads 128..191 -> d) ----
    if (tid >= 128 && tid < 128 + DV) {
        int d = tid - 128;
        float s = 0.0f;
#pragma unroll
        for (int j = 0; j < NSEQ; j++) s += vs[j * DV + d];
        vsum[d] = s;
    }

    // ---- sparse QK dots: t -> (i = t/8, slot l = t%8) ----
    for (int t = tid; t < NSEQ * 8; t += 256) {
        int i = t >> 3, l = t & 7;
        float w = 0.0f;
        if (l < cnt[i]) {
            int j = nbr[i][l];
            float dot = 0.0f;
#pragma unroll
            for (int d = 0; d < DK; d++)
                dot += qs[i * DK + d] * ks[j * (DK + 1) + d];
            w = __expf(dot * 0.125f) - 1.0f;
        }
        wgt[i][l] = w;
    }
    __syncthreads();

    // ---- normalizer ----
    if (tid < NSEQ) {
        float z = (float)NSEQ;
#pragma unroll
        for (int l = 0; l < 8; l++) z += wgt[tid][l];
        zinv[tid] = 1.0f / z;
    }
    __syncthreads();

    // ---- output: t -> (i = t/64, d = t%64) ----
    for (int t = tid; t < NSEQ * DV; t += 256) {
        int i = t >> 6, d = t & 63;
        float acc = vsum[d];
#pragma unroll
        for (int l = 0; l < 8; l++)
            acc += wgt[i][l] * vs[nbr[i][l] * DV + d];
        out[base + (size_t)i * DMODEL + d] = acc * zinv[i];
    }
}

// ---------------- launch ----------------
extern "C" void kernel_launch(void* const* d_in, const int* in_sizes, int n_in,
                              void* d_out, int out_size)
{
    const float* queries = (const float*)d_in[0];
    const float* keys    = (const float*)d_in[1];
    const float* values  = (const float*)d_in[2];
    const float* Wq      = (const float*)d_in[3];
    const float* bq      = (const float*)d_in[4];
    const float* Wk      = (const float*)d_in[5];
    const float* bk      = (const float*)d_in[6];
    const float* Wv      = (const float*)d_in[7];
    const float* bv      = (const float*)d_in[8];
    const float* Wo      = (const float*)d_in[9];
    const float* bo      = (const float*)d_in[10];

    float *q, *k, *v, *att;
    cudaGetSymbolAddress((void**)&q,   g_q);
    cudaGetSymbolAddress((void**)&k,   g_k);
    cudaGetSymbolAddress((void**)&v,   g_v);
    cudaGetSymbolAddress((void**)&att, g_att);

    // QKV projections: M=100352, N=512, K=512 (tf32 tensor cores)
    dim3 gridQKV(DMODEL / 128, MROWS / 128);
    wmma_tf32_gemm<128, 128, 32><<<gridQKV, 256>>>(
        queries, Wq, bq, q, MROWS, DMODEL, DMODEL);
    wmma_tf32_gemm<128, 128, 32><<<gridQKV, 256>>>(
        keys, Wk, bk, k, MROWS, DMODEL, DMODEL);
    wmma_tf32_gemm<128, 128, 32><<<gridQKV, 256>>>(
        values, Wv, bv, v, MROWS, DMODEL, DMODEL);

    // sparse dilated attention: one block per (b, h)
    dilate_attention_sparse<<<dim3(HEADS, BATCH), 256>>>(q, k, v, att);

    // output projection: M=100352, N=64, K=512
    dim3 gridO(1, MROWS / 128);
    wmma_tf32_gemm<128, 64, 32><<<gridO, 256>>>(
        att, Wo, bo, (float*)d_out, MROWS, 64, DMODEL);
}